// round 3
// baseline (speedup 1.0000x reference)
#include <cuda_runtime.h>
#include <cstdint>

#define NROW 2048
#define DM   1152
#define SKV  256
#define HIDN 768
#define REG  288   // DM/4

// ---------------- scratch (device globals; allocation-free) ----------------
__device__ float g_q[NROW*DM];
__device__ float g_k[SKV*DM];
__device__ float g_v[SKV*DM];
__device__ float g_ca[NROW*DM];
__device__ float g_cap2[NROW*DM];
__device__ float g_caplog[NROW*4];
__device__ float g_aclog[NROW*4];
__device__ float g_hl[4];
__device__ float g_cm[NROW];
__device__ float g_am[NROW];
__device__ int   g_cpe[NROW];
__device__ int   g_ape[NROW];
__device__ int   g_cnt[8];
__device__ int   g_off[8];
__device__ int   g_cur[8];
__device__ int   g_idx[2*NROW];
__device__ float g_H[NROW*HIDN];
__device__ float g_HR[4L*NROW*HIDN];
__device__ float g_y[NROW*DM];

// ---------------- threefry2x32-20 (exact JAX) ----------------
__device__ __forceinline__ uint32_t rotl32(uint32_t v, int r){ return (v<<r)|(v>>(32-r)); }

__device__ __forceinline__ void tf2x32(uint32_t k0, uint32_t k1, uint32_t x0, uint32_t x1,
                                       uint32_t& o0, uint32_t& o1)
{
    uint32_t ks2 = k0 ^ k1 ^ 0x1BD11BDAu;
    x0 += k0; x1 += k1;
#define TFR(r) { x0 += x1; x1 = rotl32(x1,(r)); x1 ^= x0; }
    TFR(13) TFR(15) TFR(26) TFR(6)   x0 += k1;  x1 += ks2 + 1u;
    TFR(17) TFR(29) TFR(16) TFR(24)  x0 += ks2; x1 += k0  + 2u;
    TFR(13) TFR(15) TFR(26) TFR(6)   x0 += k0;  x1 += k1  + 3u;
    TFR(17) TFR(29) TFR(16) TFR(24)  x0 += k1;  x1 += ks2 + 4u;
    TFR(13) TFR(15) TFR(26) TFR(6)   x0 += ks2; x1 += k0  + 5u;
#undef TFR
    o0 = x0; o1 = x1;
}

// jax_threefry_partitionable=True (modern default):
// random_bits(key,32,shape)[i] = o0 ^ o1 of threefry2x32(key, (hi(i), lo(i)))
// For our sizes (< 2^32), hi(i) = 0.
__device__ __forceinline__ uint32_t jax_bits_p(uint32_t k0, uint32_t k1, uint32_t i)
{
    uint32_t o0, o1;
    tf2x32(k0, k1, 0u, i, o0, o1);
    return o0 ^ o1;
}

__device__ __forceinline__ float gumbel_from_bits(uint32_t bits)
{
    uint32_t fb = (bits >> 9) | 0x3f800000u;
    float f = __uint_as_float(fb) - 1.0f;
    const float TINY = 1.17549435e-38f;
    float u = (f > 0.0f) ? f : TINY;   // == max(tiny, f*(1-tiny)+tiny) in fp32
    return -logf(-logf(u));
}

// ---------------- generic 64x64x16 SGEMM: C = A@W^T variants ----------------
// FUSED: compute two GEMMs (W1,W3) and emit silu(a1)*a3
// GATHER: A-rows gathered through per-expert index buckets
// SMODE: 0 plain store (+bias), 1 store * rowScale, 2 add * rowScale
template<int FUSED, int GATHER, int SMODE>
__global__ void gemm64(
    const float* __restrict__ A, int lda, long long aZ,
    const float* __restrict__ W1, const float* __restrict__ W3, int ldw, long long wZ,
    const float* __restrict__ bias,
    float* __restrict__ C, int ldc, long long cZ,
    const int* __restrict__ rowIdx, const int* __restrict__ bOff,
    const int* __restrict__ bCnt, int bBase,
    const float* __restrict__ rowScale,
    int M, int N, int K)
{
    const int e = blockIdx.z;
    const float* Ae  = A  + (long long)e * aZ;
    const float* W1e = W1 + (long long)e * wZ;
    const float* W3e = FUSED ? (W3 + (long long)e * wZ) : nullptr;
    float* Ce = C + (long long)e * cZ;

    int rows = M;
    const int* idx = nullptr;
    if (GATHER) { rows = bCnt[bBase + e]; idx = rowIdx + bOff[bBase + e]; }

    const int m0 = blockIdx.y * 64;
    const int n0 = blockIdx.x * 64;
    if (m0 >= rows) return;

    __shared__ float As[16][64];
    __shared__ float Bs1[16][68];
    __shared__ float Bs3[FUSED ? 16 : 1][FUSED ? 68 : 1];
    __shared__ int   rmap[64];

    const int tid = threadIdx.x;
    const int tx = tid & 15, ty = tid >> 4;

    if (tid < 64) {
        int r = m0 + tid;
        rmap[tid] = (r < rows) ? (GATHER ? idx[r] : r) : -1;
    }
    __syncthreads();

    float acc1[4][4] = {};
    float acc3[4][4] = {};

    for (int k0 = 0; k0 < K; k0 += 16) {
        #pragma unroll
        for (int l = 0; l < 4; l++) {
            int i = tid + l * 256;
            int m = i >> 4, kk = i & 15;
            int gr = rmap[m];
            As[kk][m] = (gr >= 0 && (k0 + kk) < K) ? Ae[(long long)gr * lda + k0 + kk] : 0.f;
        }
        #pragma unroll
        for (int l = 0; l < 4; l++) {
            int i = tid + l * 256;
            int n = i >> 4, kk = i & 15;
            int gn = n0 + n;
            bool ok = (gn < N) && ((k0 + kk) < K);
            Bs1[kk][n] = ok ? W1e[(long long)gn * ldw + k0 + kk] : 0.f;
            if (FUSED) Bs3[kk][n] = ok ? W3e[(long long)gn * ldw + k0 + kk] : 0.f;
        }
        __syncthreads();

        #pragma unroll
        for (int kk = 0; kk < 16; kk++) {
            float a[4], b1[4], b3[4];
            #pragma unroll
            for (int i2 = 0; i2 < 4; i2++) a[i2] = As[kk][ty*4 + i2];
            #pragma unroll
            for (int j = 0; j < 4; j++) {
                b1[j] = Bs1[kk][tx*4 + j];
                if (FUSED) b3[j] = Bs3[kk][tx*4 + j];
            }
            #pragma unroll
            for (int i2 = 0; i2 < 4; i2++)
                #pragma unroll
                for (int j = 0; j < 4; j++) {
                    acc1[i2][j] += a[i2] * b1[j];
                    if (FUSED) acc3[i2][j] += a[i2] * b3[j];
                }
        }
        __syncthreads();
    }

    #pragma unroll
    for (int i2 = 0; i2 < 4; i2++) {
        int gr = rmap[ty*4 + i2];
        if (gr < 0) continue;
        #pragma unroll
        for (int j = 0; j < 4; j++) {
            int n = n0 + tx*4 + j;
            if (n >= N) continue;
            float v;
            if (FUSED) {
                float a = acc1[i2][j];
                v = (a / (1.0f + expf(-a))) * acc3[i2][j];
            } else {
                v = acc1[i2][j];
                if (bias) v += bias[n];
            }
            long long off = (long long)gr * ldc + n;
            if (SMODE == 1)      Ce[off]  = v * rowScale[gr];
            else if (SMODE == 2) Ce[off] += v * rowScale[gr];
            else                 Ce[off]  = v;
        }
    }
}

// ---------------- attention: one block per (s,h,b), 128 threads ----------------
__global__ void attn_kernel(const float* __restrict__ Q, const float* __restrict__ Kc,
                            const float* __restrict__ Vc, float* __restrict__ O)
{
    const int s = blockIdx.x, h = blockIdx.y, b = blockIdx.z;
    const int t = threadIdx.x;

    __shared__ float qs[144];
    __shared__ float Ks[128][17];
    __shared__ float sc[128];
    __shared__ float red[4];

    const float* qp = Q + (long long)(b*1024 + s) * DM + h*144;
    for (int d = t; d < 144; d += 128) qs[d] = qp[d];
    __syncthreads();

    const float* kbase = Kc + (long long)(b*128) * DM + h*144;
    float acc = 0.f;
    for (int d0 = 0; d0 < 144; d0 += 16) {
        #pragma unroll
        for (int l = 0; l < 16; l++) {
            int i = t + l*128;
            int r = i >> 4, c = i & 15;
            Ks[r][c] = kbase[(long long)r * DM + d0 + c];
        }
        __syncthreads();
        #pragma unroll
        for (int c = 0; c < 16; c++) acc += qs[d0 + c] * Ks[t][c];
        __syncthreads();
    }

    float sv = acc * (1.0f / 12.0f);
    float v = sv;
    #pragma unroll
    for (int o = 16; o > 0; o >>= 1) v = fmaxf(v, __shfl_xor_sync(0xffffffffu, v, o));
    if ((t & 31) == 0) red[t >> 5] = v;
    __syncthreads();
    float mx = fmaxf(fmaxf(red[0], red[1]), fmaxf(red[2], red[3]));
    float ex = expf(sv - mx);
    v = ex;
    #pragma unroll
    for (int o = 16; o > 0; o >>= 1) v += __shfl_xor_sync(0xffffffffu, v, o);
    __syncthreads();
    if ((t & 31) == 0) red[t >> 5] = v;
    __syncthreads();
    float sum = red[0] + red[1] + red[2] + red[3];
    sc[t] = ex / sum;
    __syncthreads();

    const float* vbase = Vc + (long long)(b*128) * DM + h*144;
    float* op = O + (long long)(b*1024 + s) * DM + h*144;
    for (int d = t; d < 144; d += 128) {
        float o = 0.f;
        #pragma unroll 4
        for (int ks2 = 0; ks2 < 128; ks2++) o += sc[ks2] * vbase[(long long)ks2 * DM + d];
        op[d] = o;
    }
}

// ---------------- gating: exact JAX gumbel (partitionable semantics) ----------------
__global__ void init_counts()
{
    if (threadIdx.x < 8) g_cnt[threadIdx.x] = 0;
}

__global__ void gating_kernel(const float* __restrict__ caplog, const float* __restrict__ aclog)
{
    int n = blockIdx.x * blockDim.x + threadIdx.x;
    if (n >= NROW) return;

    // foldlike split: child key i = threefry2x32(parent, (0, i)) full pair
    uint32_t k1a,k1b,k2a,k2b,k3a,k3b;
    tf2x32(0u, 42u, 0u, 0u, k1a, k1b);
    tf2x32(0u, 42u, 0u, 1u, k2a, k2b);
    tf2x32(0u, 42u, 0u, 2u, k3a, k3b);

    // hl gumbel softmax (soft, temp=1): shape (2048,2), flat idx 2n+c
    float g0 = gumbel_from_bits(jax_bits_p(k1a, k1b, 2u*(uint32_t)n + 0u));
    float g1 = gumbel_from_bits(jax_bits_p(k1a, k1b, 2u*(uint32_t)n + 1u));
    int bb = n >> 10;
    float l0 = g_hl[2*bb + 0] + g0;
    float l1 = g_hl[2*bb + 1] + g1;
    float mx = fmaxf(l0, l1);
    float e0 = expf(l0 - mx), e1 = expf(l1 - mx);
    float inv = 1.0f / (e0 + e1);
    g_cm[n] = e0 * inv;
    g_am[n] = e1 * inv;

    // cap hard gumbel: shape (2048,4), flat idx 4n+c; argmax(logits+g)
    int be = 0; float bv = -1e30f;
    #pragma unroll
    for (int c = 0; c < 4; c++) {
        float g = gumbel_from_bits(jax_bits_p(k2a, k2b, 4u*(uint32_t)n + (uint32_t)c));
        float yv = caplog[n*4 + c] + g;
        if (yv > bv) { bv = yv; be = c; }
    }
    g_cpe[n] = be;
    atomicAdd(&g_cnt[be], 1);

    int ae = 0; bv = -1e30f;
    #pragma unroll
    for (int c = 0; c < 4; c++) {
        float g = gumbel_from_bits(jax_bits_p(k3a, k3b, 4u*(uint32_t)n + (uint32_t)c));
        float yv = aclog[n*4 + c] + g;
        if (yv > bv) { bv = yv; ae = c; }
    }
    g_ape[n] = ae;
    atomicAdd(&g_cnt[4 + ae], 1);
}

__global__ void offsets_kernel()
{
    int o = 0;
    for (int e = 0; e < 4; e++) { g_off[e] = o; o += g_cnt[e]; }
    o = NROW;
    for (int e = 4; e < 8; e++) { g_off[e] = o; o += g_cnt[e]; }
    for (int j = 0; j < 8; j++) g_cur[j] = g_off[j];
}

__global__ void scatter_kernel()
{
    int n = blockIdx.x * blockDim.x + threadIdx.x;
    if (n >= NROW) return;
    int e = g_cpe[n];
    int p = atomicAdd(&g_cur[e], 1);
    g_idx[p] = n;
    int a = g_ape[n];
    p = atomicAdd(&g_cur[4 + a], 1);
    g_idx[p] = n;
}

// ---------------- lb loss: deterministic single-block reduction ----------------
__global__ void lb_kernel(float* __restrict__ outp, long long i1)
{
    __shared__ float sh[256 * 9];
    int t = threadIdx.x;
    float u[8] = {0,0,0,0,0,0,0,0};
    float ms = 0.f;
    for (int n = t; n < NROW; n += 256) {
        u[g_cpe[n]]     += g_cm[n];
        u[4 + g_ape[n]] += g_am[n];
        ms += g_cm[n] + g_am[n];
    }
    #pragma unroll
    for (int j = 0; j < 8; j++) sh[t*9 + j] = u[j];
    sh[t*9 + 8] = ms;
    __syncthreads();
    for (int stride = 128; stride > 0; stride >>= 1) {
        if (t < stride)
            #pragma unroll
            for (int j = 0; j < 9; j++) sh[t*9 + j] += sh[(t + stride)*9 + j];
        __syncthreads();
    }
    if (t == 0 && i1 >= 0) {
        float denom = 4.0f * sh[8] + 1e-10f;
        float acc = 0.f;
        for (int j = 0; j < 8; j++) {
            float uu = sh[j] / denom;
            acc += uu * logf(uu + 1e-10f);
        }
        outp[i1] = acc / 8.0f;
    }
}

// ---------------- host launcher ----------------
extern "C" void kernel_launch(void* const* d_in, const int* in_sizes, int n_in,
                              void* d_out, int out_size)
{
    const float* x        = (const float*)d_in[0];
    const float* timei    = (const float*)d_in[1];
    const float* caption  = (const float*)d_in[2];
    const float* acoustic = (const float*)d_in[3];
    const float* w_in     = (const float*)d_in[4];
    const float* b_in     = (const float*)d_in[5];
    const float* w_out    = (const float*)d_in[6];
    const float* b_out    = (const float*)d_in[7];
    const float* hlw      = (const float*)d_in[8];
    const float* hlb      = (const float*)d_in[9];
    const float* cgw      = (const float*)d_in[10];
    const float* cgb      = (const float*)d_in[11];
    const float* agw      = (const float*)d_in[12];
    const float* agb      = (const float*)d_in[13];
    const float* cw1      = (const float*)d_in[14];
    const float* cw2      = (const float*)d_in[15];
    const float* cw3      = (const float*)d_in[16];
    const float* aw1      = (const float*)d_in[17];
    const float* aw2      = (const float*)d_in[18];
    const float* aw3      = (const float*)d_in[19];
    const float* fw1      = (const float*)d_in[20];
    const float* fw2      = (const float*)d_in[21];
    const float* fw3      = (const float*)d_in[22];
    float* out = (float*)d_out;

    float *pq,*pk,*pv,*pca,*pcap2,*pclog,*palog,*phl,*pcm,*pam,*pH,*pHR,*py;
    int *pidx,*poff,*pcnt;
    cudaGetSymbolAddress((void**)&pq,    g_q);
    cudaGetSymbolAddress((void**)&pk,    g_k);
    cudaGetSymbolAddress((void**)&pv,    g_v);
    cudaGetSymbolAddress((void**)&pca,   g_ca);
    cudaGetSymbolAddress((void**)&pcap2, g_cap2);
    cudaGetSymbolAddress((void**)&pclog, g_caplog);
    cudaGetSymbolAddress((void**)&palog, g_aclog);
    cudaGetSymbolAddress((void**)&phl,   g_hl);
    cudaGetSymbolAddress((void**)&pcm,   g_cm);
    cudaGetSymbolAddress((void**)&pam,   g_am);
    cudaGetSymbolAddress((void**)&pH,    g_H);
    cudaGetSymbolAddress((void**)&pHR,   g_HR);
    cudaGetSymbolAddress((void**)&py,    g_y);
    cudaGetSymbolAddress((void**)&pidx,  g_idx);
    cudaGetSymbolAddress((void**)&poff,  g_off);
    cudaGetSymbolAddress((void**)&pcnt,  g_cnt);

    // 1) Q = x @ w_in[0:D].T + b_in[0:D]
    gemm64<0,0,0><<<dim3(18,32,1),256>>>(x, DM, 0, w_in, nullptr, DM, 0, b_in,
        pq, DM, 0, nullptr, nullptr, nullptr, 0, nullptr, NROW, DM, DM);
    // 2) K, V from caption
    gemm64<0,0,0><<<dim3(18,4,1),256>>>(caption, DM, 0, w_in + (long long)DM*DM, nullptr, DM, 0,
        b_in + DM, pk, DM, 0, nullptr, nullptr, nullptr, 0, nullptr, SKV, DM, DM);
    gemm64<0,0,0><<<dim3(18,4,1),256>>>(caption, DM, 0, w_in + 2LL*DM*DM, nullptr, DM, 0,
        b_in + 2*DM, pv, DM, 0, nullptr, nullptr, nullptr, 0, nullptr, SKV, DM, DM);
    // 3) attention -> ca
    attn_kernel<<<dim3(1024,8,2),128>>>(pq, pk, pv, pca);
    // 4) cap2 = ca @ w_out.T + b_out
    gemm64<0,0,0><<<dim3(18,32,1),256>>>(pca, DM, 0, w_out, nullptr, DM, 0, b_out,
        pcap2, DM, 0, nullptr, nullptr, nullptr, 0, nullptr, NROW, DM, DM);
    // 5) hl = time @ hl_w.T + hl_b  (2x2)
    gemm64<0,0,0><<<dim3(1,1,1),256>>>(timei, DM, 0, hlw, nullptr, DM, 0, hlb,
        phl, 2, 0, nullptr, nullptr, nullptr, 0, nullptr, 2, 2, DM);
    // 6) gate logits
    gemm64<0,0,0><<<dim3(1,32,1),256>>>(pcap2, DM, 0, cgw, nullptr, DM, 0, cgb,
        pclog, 4, 0, nullptr, nullptr, nullptr, 0, nullptr, NROW, 4, DM);
    gemm64<0,0,0><<<dim3(1,32,1),256>>>(acoustic, DM, 0, agw, nullptr, DM, 0, agb,
        palog, 4, 0, nullptr, nullptr, nullptr, 0, nullptr, NROW, 4, DM);
    // 7) gating (exact threefry gumbel, partitionable)
    init_counts<<<1,32>>>();
    gating_kernel<<<8,256>>>(pclog, palog);
    offsets_kernel<<<1,1>>>();
    scatter_kernel<<<8,256>>>();
    // 8) MoE cap branch (top-1 routed)
    gemm64<1,1,0><<<dim3(12,32,4),256>>>(x, DM, 0, cw1, cw3, DM, (long long)HIDN*DM, nullptr,
        pH, HIDN, 0, pidx, poff, pcnt, 0, nullptr, NROW, HIDN, DM);
    gemm64<0,1,1><<<dim3(18,32,4),256>>>(pH, HIDN, 0, cw2, nullptr, HIDN, (long long)DM*HIDN, nullptr,
        py, DM, 0, pidx, poff, pcnt, 0, pcm, NROW, DM, HIDN);
    // 9) MoE ac branch
    gemm64<1,1,0><<<dim3(12,32,4),256>>>(x, DM, 0, aw1, aw3, DM, (long long)HIDN*DM, nullptr,
        pH, HIDN, 0, pidx, poff, pcnt, 4, nullptr, NROW, HIDN, DM);
    gemm64<0,1,2><<<dim3(18,32,4),256>>>(pH, HIDN, 0, aw2, nullptr, HIDN, (long long)DM*HIDN, nullptr,
        py, DM, 0, pidx, poff, pcnt, 4, pam, NROW, DM, HIDN);
    // 10) region FF: up (silu fused) then down into d_out column slices
    gemm64<1,0,0><<<dim3(12,32,4),256>>>(py, DM, REG, fw1, fw3, DM, (long long)(HIDN*DM + REG), nullptr,
        pHR, HIDN, (long long)NROW*HIDN, nullptr, nullptr, nullptr, 0, nullptr, NROW, HIDN, REG);
    gemm64<0,0,0><<<dim3(5,32,4),256>>>(pHR, HIDN, (long long)NROW*HIDN, fw2, nullptr, HIDN,
        (long long)(DM*HIDN + REG*HIDN), nullptr,
        out, DM, REG, nullptr, nullptr, nullptr, 0, nullptr, NROW, REG, HIDN);
    // 11) lb loss scalar (only if buffer extends past z)
    long long zElems = (long long)NROW * DM;           // 2359296
    long long i1 = ((long long)out_size > zElems) ? zElems : -1;
    lb_kernel<<<1,256>>>(out, i1);
}

// round 4
// speedup vs baseline: 1.4774x; 1.4774x over previous
#include <cuda_runtime.h>
#include <cstdint>

#define NROW 2048
#define DM   1152
#define SKV  256
#define HIDN 768
#define REG  288   // DM/4

// ---------------- scratch (device globals; allocation-free) ----------------
__device__ float g_q[NROW*DM];
__device__ float g_k[SKV*DM];
__device__ float g_v[SKV*DM];
__device__ float g_ca[NROW*DM];
__device__ float g_cap2[NROW*DM];
__device__ float g_caplog[NROW*4];
__device__ float g_aclog[NROW*4];
__device__ float g_hl[4];
__device__ float g_cm[NROW];
__device__ float g_am[NROW];
__device__ int   g_cpe[NROW];
__device__ int   g_ape[NROW];
__device__ int   g_cnt[8];
__device__ int   g_off[8];
__device__ int   g_cur[8];
__device__ int   g_idx[2*NROW];
__device__ float g_H1[NROW*HIDN];
__device__ float g_H3[NROW*HIDN];
__device__ float g_H [NROW*HIDN];
__device__ float g_R1[4L*NROW*HIDN];
__device__ float g_R3[4L*NROW*HIDN];
__device__ float g_R [4L*NROW*HIDN];
__device__ float g_y[NROW*DM];

// ---------------- threefry2x32-20 (exact JAX, partitionable) ----------------
__device__ __forceinline__ uint32_t rotl32(uint32_t v, int r){ return (v<<r)|(v>>(32-r)); }

__device__ __forceinline__ void tf2x32(uint32_t k0, uint32_t k1, uint32_t x0, uint32_t x1,
                                       uint32_t& o0, uint32_t& o1)
{
    uint32_t ks2 = k0 ^ k1 ^ 0x1BD11BDAu;
    x0 += k0; x1 += k1;
#define TFR(r) { x0 += x1; x1 = rotl32(x1,(r)); x1 ^= x0; }
    TFR(13) TFR(15) TFR(26) TFR(6)   x0 += k1;  x1 += ks2 + 1u;
    TFR(17) TFR(29) TFR(16) TFR(24)  x0 += ks2; x1 += k0  + 2u;
    TFR(13) TFR(15) TFR(26) TFR(6)   x0 += k0;  x1 += k1  + 3u;
    TFR(17) TFR(29) TFR(16) TFR(24)  x0 += k1;  x1 += ks2 + 4u;
    TFR(13) TFR(15) TFR(26) TFR(6)   x0 += ks2; x1 += k0  + 5u;
#undef TFR
    o0 = x0; o1 = x1;
}

__device__ __forceinline__ uint32_t jax_bits_p(uint32_t k0, uint32_t k1, uint32_t i)
{
    uint32_t o0, o1;
    tf2x32(k0, k1, 0u, i, o0, o1);
    return o0 ^ o1;
}

__device__ __forceinline__ float gumbel_from_bits(uint32_t bits)
{
    uint32_t fb = (bits >> 9) | 0x3f800000u;
    float f = __uint_as_float(fb) - 1.0f;
    const float TINY = 1.17549435e-38f;
    float u = (f > 0.0f) ? f : TINY;
    return -logf(-logf(u));
}

// ---------------- packed fp32x2 FMA helpers (Blackwell) ----------------
#define PACK2(out, lo, hi) asm("mov.b64 %0, {%1, %2};" : "=l"(out) : "f"(lo), "f"(hi))
#define UNPACK2(lo, hi, in) asm("mov.b64 {%0, %1}, %2;" : "=f"(lo), "=f"(hi) : "l"(in))
#define FMA2(acc, a, b) asm("fma.rn.f32x2 %0, %1, %2, %0;" : "+l"(acc) : "l"(a), "l"(b))

// ---------------- 128x128x16 SGEMM, double buffered, f32x2 inner loop -------
// C[gr][n] = sum_k A[gr][k] * W[n][k]  (+bias / rowScale epilogues)
// GATHER: A/C rows indirected through per-expert buckets
// EPI: 0 = store (+bias if non-null), 1 = store * rowScale[gr], 2 = += v*rowScale[gr]
template<int GATHER, int EPI>
__global__ __launch_bounds__(256)
void gemm128(const float* __restrict__ A, int lda, long long aOff,
             const float* __restrict__ W, int ldw, long long wOff,
             const float* __restrict__ bias,
             float* __restrict__ C, int ldc, long long cOff,
             const int* __restrict__ rowIdx, const int* __restrict__ bOff,
             const int* __restrict__ bCnt, int bBase,
             const float* __restrict__ rowScale,
             int M, int N, int K)
{
    const int e = blockIdx.z;
    A += (long long)e * aOff;
    W += (long long)e * wOff;
    C += (long long)e * cOff;
    int rows = M; const int* idx = nullptr;
    if (GATHER) { rows = bCnt[bBase+e]; idx = rowIdx + bOff[bBase+e]; }
    const int m0 = blockIdx.y * 128, n0 = blockIdx.x * 128;
    if (m0 >= rows) return;

    __shared__ float As[2][16][128];
    __shared__ float Bs[2][16][128];
    __shared__ int rmap[128];
    const int tid = threadIdx.x;
    if (tid < 128) {
        int r = m0 + tid;
        rmap[tid] = (r < rows) ? (GATHER ? idx[r] : r) : -1;
    }
    __syncthreads();

    const int tx = tid & 15, ty = tid >> 4;

    int am[2], aq[2], agr[2]; bool bok[2];
    #pragma unroll
    for (int l = 0; l < 2; l++) {
        int i = tid + l*256;
        am[l] = i >> 2; aq[l] = i & 3;
        agr[l] = rmap[am[l]];
        bok[l] = (n0 + am[l]) < N;
    }

    float4 ra[2], rb[2];
    unsigned long long acc2[8][4];
    #pragma unroll
    for (int i = 0; i < 8; i++)
        #pragma unroll
        for (int j = 0; j < 4; j++) acc2[i][j] = 0ull;

#define LOADT(k0) { \
    _Pragma("unroll") \
    for (int l = 0; l < 2; l++) { \
        ra[l] = (agr[l] >= 0) ? *(const float4*)(A + (long long)agr[l]*lda + (k0) + aq[l]*4) \
                              : make_float4(0.f,0.f,0.f,0.f); \
        rb[l] = bok[l] ? *(const float4*)(W + (long long)(n0+am[l])*ldw + (k0) + aq[l]*4) \
                       : make_float4(0.f,0.f,0.f,0.f); \
    } }

#define STORET(buf) { \
    _Pragma("unroll") \
    for (int l = 0; l < 2; l++) { \
        int kq = aq[l]*4; \
        As[buf][kq+0][am[l]] = ra[l].x; As[buf][kq+1][am[l]] = ra[l].y; \
        As[buf][kq+2][am[l]] = ra[l].z; As[buf][kq+3][am[l]] = ra[l].w; \
        Bs[buf][kq+0][am[l]] = rb[l].x; Bs[buf][kq+1][am[l]] = rb[l].y; \
        Bs[buf][kq+2][am[l]] = rb[l].z; Bs[buf][kq+3][am[l]] = rb[l].w; \
    } }

#define COMPUTET(buf) { \
    _Pragma("unroll") \
    for (int kk = 0; kk < 16; kk++) { \
        float a[8], b[8]; \
        *(float4*)a     = *(const float4*)&As[buf][kk][ty*8]; \
        *(float4*)(a+4) = *(const float4*)&As[buf][kk][ty*8+4]; \
        *(float4*)b     = *(const float4*)&Bs[buf][kk][tx*8]; \
        *(float4*)(b+4) = *(const float4*)&Bs[buf][kk][tx*8+4]; \
        unsigned long long bp[4]; \
        _Pragma("unroll") \
        for (int j = 0; j < 4; j++) PACK2(bp[j], b[2*j], b[2*j+1]); \
        _Pragma("unroll") \
        for (int i = 0; i < 8; i++) { \
            unsigned long long ap; PACK2(ap, a[i], a[i]); \
            _Pragma("unroll") \
            for (int j = 0; j < 4; j++) FMA2(acc2[i][j], ap, bp[j]); \
        } \
    } }

    LOADT(0)
    STORET(0)
    __syncthreads();
    int buf = 0;
    for (int k0 = 16; k0 < K; k0 += 16) {
        LOADT(k0)
        COMPUTET(buf)
        STORET(buf^1)
        __syncthreads();
        buf ^= 1;
    }
    COMPUTET(buf)

#undef LOADT
#undef STORET
#undef COMPUTET

    #pragma unroll
    for (int i = 0; i < 8; i++) {
        int gr = rmap[ty*8 + i];
        if (gr < 0) continue;
        float* crow = C + (long long)gr * ldc;
        float sc = (EPI >= 1) ? rowScale[gr] : 0.f;
        #pragma unroll
        for (int j = 0; j < 4; j++) {
            float v0, v1;
            UNPACK2(v0, v1, acc2[i][j]);
            int gn0 = n0 + tx*8 + 2*j;
            if (gn0 < N) {
                float v = v0;
                if (EPI == 0) { if (bias) v += bias[gn0]; crow[gn0] = v; }
                else if (EPI == 1) crow[gn0] = v * sc;
                else               crow[gn0] += v * sc;
            }
            if (gn0 + 1 < N) {
                float v = v1;
                if (EPI == 0) { if (bias) v += bias[gn0+1]; crow[gn0+1] = v; }
                else if (EPI == 1) crow[gn0+1] = v * sc;
                else               crow[gn0+1] += v * sc;
            }
        }
    }
}

// ---------------- attention: 64 queries x (head,batch) per block ------------
#define SMEM_ATTN 220160   // (144*64 + 144*128 + 128*148 + 64*132)*4 bytes

__global__ __launch_bounds__(256)
void attn2(const float* __restrict__ Q, const float* __restrict__ K,
           const float* __restrict__ V, float* __restrict__ O)
{
    extern __shared__ float sm[];
    float* Qs = sm;                          // [144][64]  (d-major)
    float* Ks = sm + 144*64;                 // [144][128] (d-major)
    float* Vs = sm + 144*64 + 144*128;       // [128][148] (k-major, padded)
    float* Ss = Vs + 128*148;                // [64][132]

    const int tid = threadIdx.x;
    const int q0 = blockIdx.x * 64;
    const int h = blockIdx.y, b = blockIdx.z;
    const long long qrow0 = (long long)b*1024 + q0;
    const int hc = h*144;

    for (int i = tid; i < 64*36; i += 256) {
        int q = i / 36, f = i % 36;
        float4 v4 = *(const float4*)(Q + (qrow0 + q)*DM + hc + f*4);
        Qs[(f*4+0)*64+q]=v4.x; Qs[(f*4+1)*64+q]=v4.y;
        Qs[(f*4+2)*64+q]=v4.z; Qs[(f*4+3)*64+q]=v4.w;
    }
    for (int i = tid; i < 128*36; i += 256) {
        int k = i / 36, f = i % 36;
        float4 v4 = *(const float4*)(K + ((long long)b*128 + k)*DM + hc + f*4);
        Ks[(f*4+0)*128+k]=v4.x; Ks[(f*4+1)*128+k]=v4.y;
        Ks[(f*4+2)*128+k]=v4.z; Ks[(f*4+3)*128+k]=v4.w;
        float4 w4 = *(const float4*)(V + ((long long)b*128 + k)*DM + hc + f*4);
        *(float4*)&Vs[k*148 + f*4] = w4;
    }
    __syncthreads();

    const int tx = tid & 15, ty = tid >> 4;

    {   // scores: S = Q @ K^T / 12
        float acc[4][8] = {};
        for (int d = 0; d < 144; d++) {
            float a[4], bv[8];
            *(float4*)a      = *(const float4*)&Qs[d*64 + ty*4];
            *(float4*)bv     = *(const float4*)&Ks[d*128 + tx*8];
            *(float4*)(bv+4) = *(const float4*)&Ks[d*128 + tx*8 + 4];
            #pragma unroll
            for (int i = 0; i < 4; i++)
                #pragma unroll
                for (int j = 0; j < 8; j++) acc[i][j] += a[i]*bv[j];
        }
        #pragma unroll
        for (int i = 0; i < 4; i++)
            #pragma unroll
            for (int j = 0; j < 8; j++)
                Ss[(ty*4+i)*132 + tx*8 + j] = acc[i][j] * (1.0f/12.0f);
    }
    __syncthreads();

    if (tid < 64) {   // softmax rows
        float* r = Ss + tid*132;
        float mx = -1e30f;
        for (int k = 0; k < 128; k++) mx = fmaxf(mx, r[k]);
        float sum = 0.f;
        for (int k = 0; k < 128; k++) { float ev = expf(r[k]-mx); r[k] = ev; sum += ev; }
        float inv = 1.0f / sum;
        for (int k = 0; k < 128; k++) r[k] *= inv;
    }
    __syncthreads();

    {   // O = S @ V
        float o[4][9] = {};
        for (int k = 0; k < 128; k++) {
            float s[4];
            #pragma unroll
            for (int i = 0; i < 4; i++) s[i] = Ss[(ty*4+i)*132 + k];
            #pragma unroll
            for (int j = 0; j < 9; j++) {
                float vv = Vs[k*148 + tx*9 + j];
                #pragma unroll
                for (int i = 0; i < 4; i++) o[i][j] += s[i]*vv;
            }
        }
        #pragma unroll
        for (int i = 0; i < 4; i++)
            #pragma unroll
            for (int j = 0; j < 9; j++)
                O[(qrow0 + ty*4 + i)*DM + hc + tx*9 + j] = o[i][j];
    }
}

// ---------------- small kernels ----------------
__global__ void silumul4(const float4* __restrict__ H1, const float4* __restrict__ H3,
                         float4* __restrict__ Hout, int n4)
{
    int i = blockIdx.x*blockDim.x + threadIdx.x;
    if (i >= n4) return;
    float4 a = H1[i], c = H3[i], r;
    r.x = a.x/(1.f+expf(-a.x))*c.x;
    r.y = a.y/(1.f+expf(-a.y))*c.y;
    r.z = a.z/(1.f+expf(-a.z))*c.z;
    r.w = a.w/(1.f+expf(-a.w))*c.w;
    Hout[i] = r;
}

// gate logits: out[w][0..3] = A[w] . W[e] + b[e]; one warp per row
__global__ void gate4(const float* __restrict__ A, const float* __restrict__ W,
                      const float* __restrict__ b, float* __restrict__ out)
{
    int w = blockIdx.x*8 + (threadIdx.x >> 5);
    int lane = threadIdx.x & 31;
    if (w >= NROW) return;
    const float* a = A + (long long)w*DM;
    float s0=0,s1=0,s2=0,s3=0;
    for (int c = lane*4; c < DM; c += 128) {
        float4 av = *(const float4*)(a + c);
        float4 w0 = *(const float4*)(W + c);
        float4 w1 = *(const float4*)(W + DM + c);
        float4 w2 = *(const float4*)(W + 2*DM + c);
        float4 w3 = *(const float4*)(W + 3*DM + c);
        s0 += av.x*w0.x + av.y*w0.y + av.z*w0.z + av.w*w0.w;
        s1 += av.x*w1.x + av.y*w1.y + av.z*w1.z + av.w*w1.w;
        s2 += av.x*w2.x + av.y*w2.y + av.z*w2.z + av.w*w2.w;
        s3 += av.x*w3.x + av.y*w3.y + av.z*w3.z + av.w*w3.w;
    }
    #pragma unroll
    for (int o = 16; o > 0; o >>= 1) {
        s0 += __shfl_xor_sync(0xffffffffu, s0, o);
        s1 += __shfl_xor_sync(0xffffffffu, s1, o);
        s2 += __shfl_xor_sync(0xffffffffu, s2, o);
        s3 += __shfl_xor_sync(0xffffffffu, s3, o);
    }
    if (lane == 0) {
        out[w*4+0] = s0 + b[0]; out[w*4+1] = s1 + b[1];
        out[w*4+2] = s2 + b[2]; out[w*4+3] = s3 + b[3];
    }
}

__global__ void hlk(const float* __restrict__ t, const float* __restrict__ w,
                    const float* __restrict__ bb, float* __restrict__ hl)
{
    int wi = threadIdx.x >> 5, lane = threadIdx.x & 31;
    int r = wi >> 1, o = wi & 1;
    const float* a = t + r*DM;
    const float* ww = w + o*DM;
    float s = 0.f;
    for (int c = lane*4; c < DM; c += 128) {
        float4 av = *(const float4*)(a + c);
        float4 wv = *(const float4*)(ww + c);
        s += av.x*wv.x + av.y*wv.y + av.z*wv.z + av.w*wv.w;
    }
    #pragma unroll
    for (int off = 16; off > 0; off >>= 1) s += __shfl_xor_sync(0xffffffffu, s, off);
    if (lane == 0) hl[r*2+o] = s + bb[o];
}

// ---------------- gating + routing ----------------
__global__ void init_counts()
{
    if (threadIdx.x < 8) g_cnt[threadIdx.x] = 0;
}

__global__ void gating_kernel(const float* __restrict__ caplog, const float* __restrict__ aclog)
{
    int n = blockIdx.x * blockDim.x + threadIdx.x;
    if (n >= NROW) return;

    uint32_t k1a,k1b,k2a,k2b,k3a,k3b;
    tf2x32(0u, 42u, 0u, 0u, k1a, k1b);
    tf2x32(0u, 42u, 0u, 1u, k2a, k2b);
    tf2x32(0u, 42u, 0u, 2u, k3a, k3b);

    float g0 = gumbel_from_bits(jax_bits_p(k1a, k1b, 2u*(uint32_t)n + 0u));
    float g1 = gumbel_from_bits(jax_bits_p(k1a, k1b, 2u*(uint32_t)n + 1u));
    int bb = n >> 10;
    float l0 = g_hl[2*bb + 0] + g0;
    float l1 = g_hl[2*bb + 1] + g1;
    float mx = fmaxf(l0, l1);
    float e0 = expf(l0 - mx), e1 = expf(l1 - mx);
    float inv = 1.0f / (e0 + e1);
    g_cm[n] = e0 * inv;
    g_am[n] = e1 * inv;

    int be = 0; float bv = -1e30f;
    #pragma unroll
    for (int c = 0; c < 4; c++) {
        float g = gumbel_from_bits(jax_bits_p(k2a, k2b, 4u*(uint32_t)n + (uint32_t)c));
        float yv = caplog[n*4 + c] + g;
        if (yv > bv) { bv = yv; be = c; }
    }
    g_cpe[n] = be;
    atomicAdd(&g_cnt[be], 1);

    int ae = 0; bv = -1e30f;
    #pragma unroll
    for (int c = 0; c < 4; c++) {
        float g = gumbel_from_bits(jax_bits_p(k3a, k3b, 4u*(uint32_t)n + (uint32_t)c));
        float yv = aclog[n*4 + c] + g;
        if (yv > bv) { bv = yv; ae = c; }
    }
    g_ape[n] = ae;
    atomicAdd(&g_cnt[4 + ae], 1);
}

__global__ void offsets_kernel()
{
    int o = 0;
    for (int e = 0; e < 4; e++) { g_off[e] = o; o += g_cnt[e]; }
    o = NROW;
    for (int e = 4; e < 8; e++) { g_off[e] = o; o += g_cnt[e]; }
    for (int j = 0; j < 8; j++) g_cur[j] = g_off[j];
}

__global__ void scatter_kernel()
{
    int n = blockIdx.x * blockDim.x + threadIdx.x;
    if (n >= NROW) return;
    int e = g_cpe[n];
    int p = atomicAdd(&g_cur[e], 1);
    g_idx[p] = n;
    int a = g_ape[n];
    p = atomicAdd(&g_cur[4 + a], 1);
    g_idx[p] = n;
}

// ---------------- lb loss ----------------
__global__ void lb_kernel(float* __restrict__ outp, long long i1)
{
    __shared__ float sh[256 * 9];
    int t = threadIdx.x;
    float u[8] = {0,0,0,0,0,0,0,0};
    float ms = 0.f;
    for (int n = t; n < NROW; n += 256) {
        u[g_cpe[n]]     += g_cm[n];
        u[4 + g_ape[n]] += g_am[n];
        ms += g_cm[n] + g_am[n];
    }
    #pragma unroll
    for (int j = 0; j < 8; j++) sh[t*9 + j] = u[j];
    sh[t*9 + 8] = ms;
    __syncthreads();
    for (int stride = 128; stride > 0; stride >>= 1) {
        if (t < stride)
            #pragma unroll
            for (int j = 0; j < 9; j++) sh[t*9 + j] += sh[(t + stride)*9 + j];
        __syncthreads();
    }
    if (t == 0 && i1 >= 0) {
        float denom = 4.0f * sh[8] + 1e-10f;
        float acc = 0.f;
        for (int j = 0; j < 8; j++) {
            float uu = sh[j] / denom;
            acc += uu * logf(uu + 1e-10f);
        }
        outp[i1] = acc / 8.0f;
    }
}

// ---------------- host launcher ----------------
extern "C" void kernel_launch(void* const* d_in, const int* in_sizes, int n_in,
                              void* d_out, int out_size)
{
    const float* x        = (const float*)d_in[0];
    const float* timei    = (const float*)d_in[1];
    const float* caption  = (const float*)d_in[2];
    const float* acoustic = (const float*)d_in[3];
    const float* w_in     = (const float*)d_in[4];
    const float* b_in     = (const float*)d_in[5];
    const float* w_out    = (const float*)d_in[6];
    const float* b_out    = (const float*)d_in[7];
    const float* hlw      = (const float*)d_in[8];
    const float* hlb      = (const float*)d_in[9];
    const float* cgw      = (const float*)d_in[10];
    const float* cgb      = (const float*)d_in[11];
    const float* agw      = (const float*)d_in[12];
    const float* agb      = (const float*)d_in[13];
    const float* cw1      = (const float*)d_in[14];
    const float* cw2      = (const float*)d_in[15];
    const float* cw3      = (const float*)d_in[16];
    const float* aw1      = (const float*)d_in[17];
    const float* aw2      = (const float*)d_in[18];
    const float* aw3      = (const float*)d_in[19];
    const float* fw1      = (const float*)d_in[20];
    const float* fw2      = (const float*)d_in[21];
    const float* fw3      = (const float*)d_in[22];
    float* out = (float*)d_out;

    float *pq,*pk,*pv,*pca,*pcap2,*pclog,*palog,*phl,*pcm,*pam;
    float *pH1,*pH3,*pH,*pR1,*pR3,*pR,*py;
    int *pidx,*poff,*pcnt;
    cudaGetSymbolAddress((void**)&pq,    g_q);
    cudaGetSymbolAddress((void**)&pk,    g_k);
    cudaGetSymbolAddress((void**)&pv,    g_v);
    cudaGetSymbolAddress((void**)&pca,   g_ca);
    cudaGetSymbolAddress((void**)&pcap2, g_cap2);
    cudaGetSymbolAddress((void**)&pclog, g_caplog);
    cudaGetSymbolAddress((void**)&palog, g_aclog);
    cudaGetSymbolAddress((void**)&phl,   g_hl);
    cudaGetSymbolAddress((void**)&pcm,   g_cm);
    cudaGetSymbolAddress((void**)&pam,   g_am);
    cudaGetSymbolAddress((void**)&pH1,   g_H1);
    cudaGetSymbolAddress((void**)&pH3,   g_H3);
    cudaGetSymbolAddress((void**)&pH,    g_H);
    cudaGetSymbolAddress((void**)&pR1,   g_R1);
    cudaGetSymbolAddress((void**)&pR3,   g_R3);
    cudaGetSymbolAddress((void**)&pR,    g_R);
    cudaGetSymbolAddress((void**)&py,    g_y);
    cudaGetSymbolAddress((void**)&pidx,  g_idx);
    cudaGetSymbolAddress((void**)&poff,  g_off);
    cudaGetSymbolAddress((void**)&pcnt,  g_cnt);

    cudaFuncSetAttribute(attn2, cudaFuncAttributeMaxDynamicSharedMemorySize, SMEM_ATTN);

    const long long HDM = (long long)HIDN*DM;
    const long long DHI = (long long)DM*HIDN;

    // 1) Q = x @ w_in[0:D].T + b
    gemm128<0,0><<<dim3(9,16,1),256>>>(x, DM, 0, w_in, DM, 0, b_in,
        pq, DM, 0, nullptr,nullptr,nullptr,0, nullptr, NROW, DM, DM);
    // 2) K, V from caption
    gemm128<0,0><<<dim3(9,2,1),256>>>(caption, DM, 0, w_in + (long long)DM*DM, DM, 0, b_in + DM,
        pk, DM, 0, nullptr,nullptr,nullptr,0, nullptr, SKV, DM, DM);
    gemm128<0,0><<<dim3(9,2,1),256>>>(caption, DM, 0, w_in + 2LL*DM*DM, DM, 0, b_in + 2*DM,
        pv, DM, 0, nullptr,nullptr,nullptr,0, nullptr, SKV, DM, DM);
    // 3) attention
    attn2<<<dim3(16,8,2),256,SMEM_ATTN>>>(pq, pk, pv, pca);
    // 4) out proj
    gemm128<0,0><<<dim3(9,16,1),256>>>(pca, DM, 0, w_out, DM, 0, b_out,
        pcap2, DM, 0, nullptr,nullptr,nullptr,0, nullptr, NROW, DM, DM);
    // 5) hl + gate logits
    hlk<<<1,128>>>(timei, hlw, hlb, phl);
    gate4<<<NROW/8,256>>>(pcap2, cgw, cgb, pclog);
    gate4<<<NROW/8,256>>>(acoustic, agw, agb, palog);
    // 6) gating + routing
    init_counts<<<1,32>>>();
    gating_kernel<<<8,256>>>(pclog, palog);
    offsets_kernel<<<1,1>>>();
    scatter_kernel<<<8,256>>>();
    // 7) MoE cap branch
    gemm128<1,0><<<dim3(6,16,4),256>>>(x, DM, 0, cw1, DM, HDM, nullptr,
        pH1, HIDN, 0, pidx,poff,pcnt,0, nullptr, NROW, HIDN, DM);
    gemm128<1,0><<<dim3(6,16,4),256>>>(x, DM, 0, cw3, DM, HDM, nullptr,
        pH3, HIDN, 0, pidx,poff,pcnt,0, nullptr, NROW, HIDN, DM);
    silumul4<<<NROW*HIDN/4/256,256>>>((const float4*)pH1,(const float4*)pH3,(float4*)pH, NROW*HIDN/4);
    gemm128<1,1><<<dim3(9,16,4),256>>>(pH, HIDN, 0, cw2, HIDN, DHI, nullptr,
        py, DM, 0, pidx,poff,pcnt,0, pcm, NROW, DM, HIDN);
    // 8) MoE ac branch
    gemm128<1,0><<<dim3(6,16,4),256>>>(x, DM, 0, aw1, DM, HDM, nullptr,
        pH1, HIDN, 0, pidx,poff,pcnt,4, nullptr, NROW, HIDN, DM);
    gemm128<1,0><<<dim3(6,16,4),256>>>(x, DM, 0, aw3, DM, HDM, nullptr,
        pH3, HIDN, 0, pidx,poff,pcnt,4, nullptr, NROW, HIDN, DM);
    silumul4<<<NROW*HIDN/4/256,256>>>((const float4*)pH1,(const float4*)pH3,(float4*)pH, NROW*HIDN/4);
    gemm128<1,2><<<dim3(9,16,4),256>>>(pH, HIDN, 0, aw2, HIDN, DHI, nullptr,
        py, DM, 0, pidx,poff,pcnt,4, pam, NROW, DM, HIDN);
    // 9) region FF (expert e sees/produces column slice e*288..)
    gemm128<0,0><<<dim3(6,16,4),256>>>(py, DM, REG, fw1, DM, HDM + REG, nullptr,
        pR1, HIDN, (long long)NROW*HIDN, nullptr,nullptr,nullptr,0, nullptr, NROW, HIDN, REG);
    gemm128<0,0><<<dim3(6,16,4),256>>>(py, DM, REG, fw3, DM, HDM + REG, nullptr,
        pR3, HIDN, (long long)NROW*HIDN, nullptr,nullptr,nullptr,0, nullptr, NROW, HIDN, REG);
    silumul4<<<4*NROW*HIDN/4/256,256>>>((const float4*)pR1,(const float4*)pR3,(float4*)pR, 4*NROW*HIDN/4);
    gemm128<0,0><<<dim3(3,16,4),256>>>(pR, HIDN, (long long)NROW*HIDN, fw2, HIDN, DHI + (long long)REG*HIDN, nullptr,
        out, DM, REG, nullptr,nullptr,nullptr,0, nullptr, NROW, REG, HIDN);
    // 10) lb loss scalar
    long long zElems = (long long)NROW * DM;
    long long i1 = ((long long)out_size > zElems) ? zElems : -1;
    lb_kernel<<<1,256>>>(out, i1);
}

// round 5
// speedup vs baseline: 2.3057x; 1.5606x over previous
#include <cuda_runtime.h>
#include <cstdint>

#define NROW 2048
#define DM   1152
#define SKV  256
#define HIDN 768
#define REG  288   // DM/4

// ---------------- scratch (device globals; allocation-free) ----------------
__device__ float g_q[NROW*DM];
__device__ float g_k[SKV*DM];
__device__ float g_v[SKV*DM];
__device__ float g_ca[NROW*DM];
__device__ float g_cap2[NROW*DM];
__device__ float g_caplog[NROW*4];
__device__ float g_aclog[NROW*4];
__device__ float g_hl[4];
__device__ float g_cm[NROW];
__device__ float g_am[NROW];
__device__ int   g_cpe[NROW];
__device__ int   g_ape[NROW];
__device__ int   g_cnt[8];
__device__ int   g_off[8];
__device__ int   g_cur[8];
__device__ int   g_idx[2*NROW];
__device__ float g_H1[NROW*HIDN];
__device__ float g_H3[NROW*HIDN];
__device__ float g_H [NROW*HIDN];
__device__ float g_R1[4L*NROW*HIDN];
__device__ float g_R3[4L*NROW*HIDN];
__device__ float g_R [4L*NROW*HIDN];
__device__ float g_y[NROW*DM];

// ---------------- threefry2x32-20 (exact JAX, partitionable) ----------------
__device__ __forceinline__ uint32_t rotl32(uint32_t v, int r){ return (v<<r)|(v>>(32-r)); }

__device__ __forceinline__ void tf2x32(uint32_t k0, uint32_t k1, uint32_t x0, uint32_t x1,
                                       uint32_t& o0, uint32_t& o1)
{
    uint32_t ks2 = k0 ^ k1 ^ 0x1BD11BDAu;
    x0 += k0; x1 += k1;
#define TFR(r) { x0 += x1; x1 = rotl32(x1,(r)); x1 ^= x0; }
    TFR(13) TFR(15) TFR(26) TFR(6)   x0 += k1;  x1 += ks2 + 1u;
    TFR(17) TFR(29) TFR(16) TFR(24)  x0 += ks2; x1 += k0  + 2u;
    TFR(13) TFR(15) TFR(26) TFR(6)   x0 += k0;  x1 += k1  + 3u;
    TFR(17) TFR(29) TFR(16) TFR(24)  x0 += k1;  x1 += ks2 + 4u;
    TFR(13) TFR(15) TFR(26) TFR(6)   x0 += ks2; x1 += k0  + 5u;
#undef TFR
    o0 = x0; o1 = x1;
}

__device__ __forceinline__ uint32_t jax_bits_p(uint32_t k0, uint32_t k1, uint32_t i)
{
    uint32_t o0, o1;
    tf2x32(k0, k1, 0u, i, o0, o1);
    return o0 ^ o1;
}

__device__ __forceinline__ float gumbel_from_bits(uint32_t bits)
{
    uint32_t fb = (bits >> 9) | 0x3f800000u;
    float f = __uint_as_float(fb) - 1.0f;
    const float TINY = 1.17549435e-38f;
    float u = (f > 0.0f) ? f : TINY;
    return -logf(-logf(u));
}

// ---------------- tf32 tensor-core GEMM (3xTF32 compensated) ----------------
// C[gr][n] = sum_k A[gr][k] * W[n][k]
// Block tile 128(M) x 64(N) x 32(K); 128 threads (4 warps, warp tile 64x32).
// 3xTF32: a = ahi + alo (hi = mask 13 low mantissa bits), same for b;
//         D += ahi*bhi + ahi*blo + alo*bhi  (error ~2^-24, fp32-grade)
// GATHER: rows indirected via per-expert buckets. EPI: 0 store(+bias),
// 1 store*rowScale[gr], 2 +='s *rowScale[gr].

__device__ __forceinline__ void mma8(float* d, const uint32_t* a, const uint32_t* b)
{
    asm volatile(
        "mma.sync.aligned.m16n8k8.row.col.f32.tf32.tf32.f32 "
        "{%0,%1,%2,%3}, {%4,%5,%6,%7}, {%8,%9}, {%0,%1,%2,%3};\n"
        : "+f"(d[0]), "+f"(d[1]), "+f"(d[2]), "+f"(d[3])
        : "r"(a[0]), "r"(a[1]), "r"(a[2]), "r"(a[3]), "r"(b[0]), "r"(b[1]));
}

#define LDM_A 136   // As[k][m], 32 x 136 floats
#define LDN_B 36    // Bs[n][k], 64 x 36 floats
#define SMEM_GEMM (2*32*LDM_A*4 + 2*64*LDN_B*4 + 128*4)

template<int GATHER, int EPI>
__global__ __launch_bounds__(128)
void gemm_tc(const float* __restrict__ A, int lda, long long aOff,
             const float* __restrict__ W, int ldw, long long wOff,
             const float* __restrict__ bias,
             float* __restrict__ C, int ldc, long long cOff,
             const int* __restrict__ rowIdx, const int* __restrict__ bOff,
             const int* __restrict__ bCnt, int bBase,
             const float* __restrict__ rowScale,
             int M, int N, int K)
{
    extern __shared__ float sm[];
    float* As = sm;                         // [2][32][LDM_A]
    float* Bs = sm + 2*32*LDM_A;            // [2][64][LDN_B]
    int* rmap = (int*)(sm + 2*32*LDM_A + 2*64*LDN_B);

    const int e = blockIdx.z;
    A += (long long)e * aOff;
    W += (long long)e * wOff;
    C += (long long)e * cOff;
    int rows = M; const int* idx = nullptr;
    if (GATHER) { rows = bCnt[bBase+e]; idx = rowIdx + bOff[bBase+e]; }
    const int m0 = blockIdx.y * 128, n0 = blockIdx.x * 64;
    if (m0 >= rows) return;

    const int tid = threadIdx.x;
    const int warp = tid >> 5, lane = tid & 31;
    const int wm = warp >> 1, wn = warp & 1;
    const int g = lane >> 2, tq = lane & 3;

    {
        int r = m0 + tid;
        rmap[tid] = (r < rows) ? (GATHER ? idx[r] : r) : -1;
    }
    __syncthreads();

    // A loader: this thread owns tile row m = tid (8 float4 per BK=32)
    const int agr = rmap[tid];
    const float* arow = (agr >= 0) ? (A + (long long)agr * lda) : nullptr;
    // B loader: row n = tid & 63, k-half = tid >> 6
    const int bn = tid & 63;
    const int bkh = tid >> 6;
    const bool bvalid = (n0 + bn) < N;
    const float* brow = bvalid ? (W + (long long)(n0 + bn) * ldw + bkh * 16) : nullptr;

    float4 ra[8], rb[4];
    float d[4][4][4];
    #pragma unroll
    for (int i = 0; i < 4; i++)
        #pragma unroll
        for (int j = 0; j < 4; j++)
            #pragma unroll
            for (int r = 0; r < 4; r++) d[i][j][r] = 0.f;

    const float4 z4 = make_float4(0.f,0.f,0.f,0.f);

#define LOADT(k0) { \
    _Pragma("unroll") \
    for (int l = 0; l < 8; l++) ra[l] = arow ? *(const float4*)(arow + (k0) + l*4) : z4; \
    _Pragma("unroll") \
    for (int l = 0; l < 4; l++) rb[l] = brow ? *(const float4*)(brow + (k0) + l*4) : z4; \
    }

#define STORET(buf) { \
    float* ap = As + (buf)*32*LDM_A + tid; \
    _Pragma("unroll") \
    for (int l = 0; l < 8; l++) { \
        ap[(l*4+0)*LDM_A] = ra[l].x; ap[(l*4+1)*LDM_A] = ra[l].y; \
        ap[(l*4+2)*LDM_A] = ra[l].z; ap[(l*4+3)*LDM_A] = ra[l].w; \
    } \
    float* bp = Bs + (buf)*64*LDN_B + bn*LDN_B + bkh*16; \
    _Pragma("unroll") \
    for (int l = 0; l < 4; l++) { \
        bp[l*4+0] = rb[l].x; bp[l*4+1] = rb[l].y; \
        bp[l*4+2] = rb[l].z; bp[l*4+3] = rb[l].w; \
    } }

#define HIMASK 0xFFFFE000u

#define COMPUTET(buf) { \
    const float* ab = As + (buf)*32*LDM_A; \
    const float* bb = Bs + (buf)*64*LDN_B; \
    _Pragma("unroll") \
    for (int kc = 0; kc < 4; kc++) { \
        int k = kc*8 + tq; \
        uint32_t bhi[4][2]; uint32_t blo[4][2]; \
        _Pragma("unroll") \
        for (int nt = 0; nt < 4; nt++) { \
            int n = wn*32 + nt*8 + g; \
            float b0 = bb[n*LDN_B + k], b1 = bb[n*LDN_B + k + 4]; \
            bhi[nt][0] = __float_as_uint(b0) & HIMASK; \
            bhi[nt][1] = __float_as_uint(b1) & HIMASK; \
            blo[nt][0] = __float_as_uint(b0 - __uint_as_float(bhi[nt][0])); \
            blo[nt][1] = __float_as_uint(b1 - __uint_as_float(bhi[nt][1])); \
        } \
        _Pragma("unroll") \
        for (int mt = 0; mt < 4; mt++) { \
            int m = wm*64 + mt*16 + g; \
            float a0 = ab[k*LDM_A + m],     a1 = ab[k*LDM_A + m + 8]; \
            float a2 = ab[(k+4)*LDM_A + m], a3 = ab[(k+4)*LDM_A + m + 8]; \
            uint32_t ahi[4], alo[4]; \
            ahi[0] = __float_as_uint(a0) & HIMASK; alo[0] = __float_as_uint(a0 - __uint_as_float(ahi[0])); \
            ahi[1] = __float_as_uint(a1) & HIMASK; alo[1] = __float_as_uint(a1 - __uint_as_float(ahi[1])); \
            ahi[2] = __float_as_uint(a2) & HIMASK; alo[2] = __float_as_uint(a2 - __uint_as_float(ahi[2])); \
            ahi[3] = __float_as_uint(a3) & HIMASK; alo[3] = __float_as_uint(a3 - __uint_as_float(ahi[3])); \
            _Pragma("unroll") \
            for (int nt = 0; nt < 4; nt++) { \
                mma8(d[mt][nt], ahi, bhi[nt]); \
                mma8(d[mt][nt], ahi, blo[nt]); \
                mma8(d[mt][nt], alo, bhi[nt]); \
            } \
        } \
    } }

    LOADT(0)
    STORET(0)
    __syncthreads();
    int buf = 0;
    for (int k0 = 32; k0 < K; k0 += 32) {
        LOADT(k0)
        COMPUTET(buf)
        STORET(buf^1)
        __syncthreads();
        buf ^= 1;
    }
    COMPUTET(buf)

#undef LOADT
#undef STORET
#undef COMPUTET

    // epilogue
    #pragma unroll
    for (int mt = 0; mt < 4; mt++) {
        #pragma unroll
        for (int h = 0; h < 2; h++) {
            int r = wm*64 + mt*16 + g + 8*h;
            int gr = rmap[r];
            if (gr < 0) continue;
            float* crow = C + (long long)gr * ldc;
            float sc = (EPI >= 1) ? rowScale[gr] : 0.f;
            #pragma unroll
            for (int nt = 0; nt < 4; nt++) {
                int c0 = n0 + wn*32 + nt*8 + tq*2;
                if (c0 >= N) continue;
                float v0 = d[mt][nt][h*2+0];
                float v1 = d[mt][nt][h*2+1];
                if (EPI == 0) {
                    if (bias) { v0 += bias[c0]; v1 += bias[c0+1]; }
                    *(float2*)(crow + c0) = make_float2(v0, v1);
                } else if (EPI == 1) {
                    *(float2*)(crow + c0) = make_float2(v0*sc, v1*sc);
                } else {
                    float2 old = *(float2*)(crow + c0);
                    *(float2*)(crow + c0) = make_float2(old.x + v0*sc, old.y + v1*sc);
                }
            }
        }
    }
}

// ---------------- attention: 64 queries x (head,batch) per block ------------
#define SMEM_ATTN 220160

__global__ __launch_bounds__(256)
void attn2(const float* __restrict__ Q, const float* __restrict__ K,
           const float* __restrict__ V, float* __restrict__ O)
{
    extern __shared__ float smatt[];
    float* Qs = smatt;
    float* Ks = smatt + 144*64;
    float* Vs = smatt + 144*64 + 144*128;
    float* Ss = Vs + 128*148;

    const int tid = threadIdx.x;
    const int q0 = blockIdx.x * 64;
    const int h = blockIdx.y, b = blockIdx.z;
    const long long qrow0 = (long long)b*1024 + q0;
    const int hc = h*144;

    for (int i = tid; i < 64*36; i += 256) {
        int q = i / 36, f = i % 36;
        float4 v4 = *(const float4*)(Q + (qrow0 + q)*DM + hc + f*4);
        Qs[(f*4+0)*64+q]=v4.x; Qs[(f*4+1)*64+q]=v4.y;
        Qs[(f*4+2)*64+q]=v4.z; Qs[(f*4+3)*64+q]=v4.w;
    }
    for (int i = tid; i < 128*36; i += 256) {
        int k = i / 36, f = i % 36;
        float4 v4 = *(const float4*)(K + ((long long)b*128 + k)*DM + hc + f*4);
        Ks[(f*4+0)*128+k]=v4.x; Ks[(f*4+1)*128+k]=v4.y;
        Ks[(f*4+2)*128+k]=v4.z; Ks[(f*4+3)*128+k]=v4.w;
        float4 w4 = *(const float4*)(V + ((long long)b*128 + k)*DM + hc + f*4);
        *(float4*)&Vs[k*148 + f*4] = w4;
    }
    __syncthreads();

    const int tx = tid & 15, ty = tid >> 4;

    {
        float acc[4][8] = {};
        for (int d = 0; d < 144; d++) {
            float a[4], bv[8];
            *(float4*)a      = *(const float4*)&Qs[d*64 + ty*4];
            *(float4*)bv     = *(const float4*)&Ks[d*128 + tx*8];
            *(float4*)(bv+4) = *(const float4*)&Ks[d*128 + tx*8 + 4];
            #pragma unroll
            for (int i = 0; i < 4; i++)
                #pragma unroll
                for (int j = 0; j < 8; j++) acc[i][j] += a[i]*bv[j];
        }
        #pragma unroll
        for (int i = 0; i < 4; i++)
            #pragma unroll
            for (int j = 0; j < 8; j++)
                Ss[(ty*4+i)*132 + tx*8 + j] = acc[i][j] * (1.0f/12.0f);
    }
    __syncthreads();

    if (tid < 64) {
        float* r = Ss + tid*132;
        float mx = -1e30f;
        for (int k = 0; k < 128; k++) mx = fmaxf(mx, r[k]);
        float sum = 0.f;
        for (int k = 0; k < 128; k++) { float ev = expf(r[k]-mx); r[k] = ev; sum += ev; }
        float inv = 1.0f / sum;
        for (int k = 0; k < 128; k++) r[k] *= inv;
    }
    __syncthreads();

    {
        float o[4][9] = {};
        for (int k = 0; k < 128; k++) {
            float s[4];
            #pragma unroll
            for (int i = 0; i < 4; i++) s[i] = Ss[(ty*4+i)*132 + k];
            #pragma unroll
            for (int j = 0; j < 9; j++) {
                float vv = Vs[k*148 + tx*9 + j];
                #pragma unroll
                for (int i = 0; i < 4; i++) o[i][j] += s[i]*vv;
            }
        }
        #pragma unroll
        for (int i = 0; i < 4; i++)
            #pragma unroll
            for (int j = 0; j < 9; j++)
                O[(qrow0 + ty*4 + i)*DM + hc + tx*9 + j] = o[i][j];
    }
}

// ---------------- small kernels ----------------
__global__ void silumul4(const float4* __restrict__ H1, const float4* __restrict__ H3,
                         float4* __restrict__ Hout, int n4)
{
    int i = blockIdx.x*blockDim.x + threadIdx.x;
    if (i >= n4) return;
    float4 a = H1[i], c = H3[i], r;
    r.x = a.x/(1.f+expf(-a.x))*c.x;
    r.y = a.y/(1.f+expf(-a.y))*c.y;
    r.z = a.z/(1.f+expf(-a.z))*c.z;
    r.w = a.w/(1.f+expf(-a.w))*c.w;
    Hout[i] = r;
}

__global__ void gate4(const float* __restrict__ A, const float* __restrict__ W,
                      const float* __restrict__ b, float* __restrict__ out)
{
    int w = blockIdx.x*8 + (threadIdx.x >> 5);
    int lane = threadIdx.x & 31;
    if (w >= NROW) return;
    const float* a = A + (long long)w*DM;
    float s0=0,s1=0,s2=0,s3=0;
    for (int c = lane*4; c < DM; c += 128) {
        float4 av = *(const float4*)(a + c);
        float4 w0 = *(const float4*)(W + c);
        float4 w1 = *(const float4*)(W + DM + c);
        float4 w2 = *(const float4*)(W + 2*DM + c);
        float4 w3 = *(const float4*)(W + 3*DM + c);
        s0 += av.x*w0.x + av.y*w0.y + av.z*w0.z + av.w*w0.w;
        s1 += av.x*w1.x + av.y*w1.y + av.z*w1.z + av.w*w1.w;
        s2 += av.x*w2.x + av.y*w2.y + av.z*w2.z + av.w*w2.w;
        s3 += av.x*w3.x + av.y*w3.y + av.z*w3.z + av.w*w3.w;
    }
    #pragma unroll
    for (int o = 16; o > 0; o >>= 1) {
        s0 += __shfl_xor_sync(0xffffffffu, s0, o);
        s1 += __shfl_xor_sync(0xffffffffu, s1, o);
        s2 += __shfl_xor_sync(0xffffffffu, s2, o);
        s3 += __shfl_xor_sync(0xffffffffu, s3, o);
    }
    if (lane == 0) {
        out[w*4+0] = s0 + b[0]; out[w*4+1] = s1 + b[1];
        out[w*4+2] = s2 + b[2]; out[w*4+3] = s3 + b[3];
    }
}

__global__ void hlk(const float* __restrict__ t, const float* __restrict__ w,
                    const float* __restrict__ bb, float* __restrict__ hl)
{
    int wi = threadIdx.x >> 5, lane = threadIdx.x & 31;
    int r = wi >> 1, o = wi & 1;
    const float* a = t + r*DM;
    const float* ww = w + o*DM;
    float s = 0.f;
    for (int c = lane*4; c < DM; c += 128) {
        float4 av = *(const float4*)(a + c);
        float4 wv = *(const float4*)(ww + c);
        s += av.x*wv.x + av.y*wv.y + av.z*wv.z + av.w*wv.w;
    }
    #pragma unroll
    for (int off = 16; off > 0; off >>= 1) s += __shfl_xor_sync(0xffffffffu, s, off);
    if (lane == 0) hl[r*2+o] = s + bb[o];
}

// ---------------- gating + routing ----------------
__global__ void init_counts()
{
    if (threadIdx.x < 8) g_cnt[threadIdx.x] = 0;
}

__global__ void gating_kernel(const float* __restrict__ caplog, const float* __restrict__ aclog)
{
    int n = blockIdx.x * blockDim.x + threadIdx.x;
    if (n >= NROW) return;

    uint32_t k1a,k1b,k2a,k2b,k3a,k3b;
    tf2x32(0u, 42u, 0u, 0u, k1a, k1b);
    tf2x32(0u, 42u, 0u, 1u, k2a, k2b);
    tf2x32(0u, 42u, 0u, 2u, k3a, k3b);

    float g0 = gumbel_from_bits(jax_bits_p(k1a, k1b, 2u*(uint32_t)n + 0u));
    float g1 = gumbel_from_bits(jax_bits_p(k1a, k1b, 2u*(uint32_t)n + 1u));
    int bb = n >> 10;
    float l0 = g_hl[2*bb + 0] + g0;
    float l1 = g_hl[2*bb + 1] + g1;
    float mx = fmaxf(l0, l1);
    float e0 = expf(l0 - mx), e1 = expf(l1 - mx);
    float inv = 1.0f / (e0 + e1);
    g_cm[n] = e0 * inv;
    g_am[n] = e1 * inv;

    int be = 0; float bv = -1e30f;
    #pragma unroll
    for (int c = 0; c < 4; c++) {
        float g = gumbel_from_bits(jax_bits_p(k2a, k2b, 4u*(uint32_t)n + (uint32_t)c));
        float yv = caplog[n*4 + c] + g;
        if (yv > bv) { bv = yv; be = c; }
    }
    g_cpe[n] = be;
    atomicAdd(&g_cnt[be], 1);

    int ae = 0; bv = -1e30f;
    #pragma unroll
    for (int c = 0; c < 4; c++) {
        float g = gumbel_from_bits(jax_bits_p(k3a, k3b, 4u*(uint32_t)n + (uint32_t)c));
        float yv = aclog[n*4 + c] + g;
        if (yv > bv) { bv = yv; ae = c; }
    }
    g_ape[n] = ae;
    atomicAdd(&g_cnt[4 + ae], 1);
}

__global__ void offsets_kernel()
{
    int o = 0;
    for (int e = 0; e < 4; e++) { g_off[e] = o; o += g_cnt[e]; }
    o = NROW;
    for (int e = 4; e < 8; e++) { g_off[e] = o; o += g_cnt[e]; }
    for (int j = 0; j < 8; j++) g_cur[j] = g_off[j];
}

__global__ void scatter_kernel()
{
    int n = blockIdx.x * blockDim.x + threadIdx.x;
    if (n >= NROW) return;
    int e = g_cpe[n];
    int p = atomicAdd(&g_cur[e], 1);
    g_idx[p] = n;
    int a = g_ape[n];
    p = atomicAdd(&g_cur[4 + a], 1);
    g_idx[p] = n;
}

// ---------------- lb loss ----------------
__global__ void lb_kernel(float* __restrict__ outp, long long i1)
{
    __shared__ float sh[256 * 9];
    int t = threadIdx.x;
    float u[8] = {0,0,0,0,0,0,0,0};
    float ms = 0.f;
    for (int n = t; n < NROW; n += 256) {
        u[g_cpe[n]]     += g_cm[n];
        u[4 + g_ape[n]] += g_am[n];
        ms += g_cm[n] + g_am[n];
    }
    #pragma unroll
    for (int j = 0; j < 8; j++) sh[t*9 + j] = u[j];
    sh[t*9 + 8] = ms;
    __syncthreads();
    for (int stride = 128; stride > 0; stride >>= 1) {
        if (t < stride)
            #pragma unroll
            for (int j = 0; j < 9; j++) sh[t*9 + j] += sh[(t + stride)*9 + j];
        __syncthreads();
    }
    if (t == 0 && i1 >= 0) {
        float denom = 4.0f * sh[8] + 1e-10f;
        float acc = 0.f;
        for (int j = 0; j < 8; j++) {
            float uu = sh[j] / denom;
            acc += uu * logf(uu + 1e-10f);
        }
        outp[i1] = acc / 8.0f;
    }
}

// ---------------- host launcher ----------------
extern "C" void kernel_launch(void* const* d_in, const int* in_sizes, int n_in,
                              void* d_out, int out_size)
{
    const float* x        = (const float*)d_in[0];
    const float* timei    = (const float*)d_in[1];
    const float* caption  = (const float*)d_in[2];
    const float* acoustic = (const float*)d_in[3];
    const float* w_in     = (const float*)d_in[4];
    const float* b_in     = (const float*)d_in[5];
    const float* w_out    = (const float*)d_in[6];
    const float* b_out    = (const float*)d_in[7];
    const float* hlw      = (const float*)d_in[8];
    const float* hlb      = (const float*)d_in[9];
    const float* cgw      = (const float*)d_in[10];
    const float* cgb      = (const float*)d_in[11];
    const float* agw      = (const float*)d_in[12];
    const float* agb      = (const float*)d_in[13];
    const float* cw1      = (const float*)d_in[14];
    const float* cw2      = (const float*)d_in[15];
    const float* cw3      = (const float*)d_in[16];
    const float* aw1      = (const float*)d_in[17];
    const float* aw2      = (const float*)d_in[18];
    const float* aw3      = (const float*)d_in[19];
    const float* fw1      = (const float*)d_in[20];
    const float* fw2      = (const float*)d_in[21];
    const float* fw3      = (const float*)d_in[22];
    float* out = (float*)d_out;

    float *pq,*pk,*pv,*pca,*pcap2,*pclog,*palog,*phl,*pcm,*pam;
    float *pH1,*pH3,*pH,*pR1,*pR3,*pR,*py;
    int *pidx,*poff,*pcnt;
    cudaGetSymbolAddress((void**)&pq,    g_q);
    cudaGetSymbolAddress((void**)&pk,    g_k);
    cudaGetSymbolAddress((void**)&pv,    g_v);
    cudaGetSymbolAddress((void**)&pca,   g_ca);
    cudaGetSymbolAddress((void**)&pcap2, g_cap2);
    cudaGetSymbolAddress((void**)&pclog, g_caplog);
    cudaGetSymbolAddress((void**)&palog, g_aclog);
    cudaGetSymbolAddress((void**)&phl,   g_hl);
    cudaGetSymbolAddress((void**)&pcm,   g_cm);
    cudaGetSymbolAddress((void**)&pam,   g_am);
    cudaGetSymbolAddress((void**)&pH1,   g_H1);
    cudaGetSymbolAddress((void**)&pH3,   g_H3);
    cudaGetSymbolAddress((void**)&pH,    g_H);
    cudaGetSymbolAddress((void**)&pR1,   g_R1);
    cudaGetSymbolAddress((void**)&pR3,   g_R3);
    cudaGetSymbolAddress((void**)&pR,    g_R);
    cudaGetSymbolAddress((void**)&py,    g_y);
    cudaGetSymbolAddress((void**)&pidx,  g_idx);
    cudaGetSymbolAddress((void**)&poff,  g_off);
    cudaGetSymbolAddress((void**)&pcnt,  g_cnt);

    cudaFuncSetAttribute(attn2, cudaFuncAttributeMaxDynamicSharedMemorySize, SMEM_ATTN);
    cudaFuncSetAttribute(gemm_tc<0,0>, cudaFuncAttributeMaxDynamicSharedMemorySize, SMEM_GEMM);
    cudaFuncSetAttribute(gemm_tc<1,0>, cudaFuncAttributeMaxDynamicSharedMemorySize, SMEM_GEMM);
    cudaFuncSetAttribute(gemm_tc<1,1>, cudaFuncAttributeMaxDynamicSharedMemorySize, SMEM_GEMM);
    cudaFuncSetAttribute(gemm_tc<1,2>, cudaFuncAttributeMaxDynamicSharedMemorySize, SMEM_GEMM);

    const long long HDM = (long long)HIDN*DM;
    const long long DHI = (long long)DM*HIDN;

    // 1) Q = x @ w_in[0:D].T + b
    gemm_tc<0,0><<<dim3(18,16,1),128,SMEM_GEMM>>>(x, DM, 0, w_in, DM, 0, b_in,
        pq, DM, 0, nullptr,nullptr,nullptr,0, nullptr, NROW, DM, DM);
    // 2) K, V from caption
    gemm_tc<0,0><<<dim3(18,2,1),128,SMEM_GEMM>>>(caption, DM, 0, w_in + (long long)DM*DM, DM, 0, b_in + DM,
        pk, DM, 0, nullptr,nullptr,nullptr,0, nullptr, SKV, DM, DM);
    gemm_tc<0,0><<<dim3(18,2,1),128,SMEM_GEMM>>>(caption, DM, 0, w_in + 2LL*DM*DM, DM, 0, b_in + 2*DM,
        pv, DM, 0, nullptr,nullptr,nullptr,0, nullptr, SKV, DM, DM);
    // 3) attention
    attn2<<<dim3(16,8,2),256,SMEM_ATTN>>>(pq, pk, pv, pca);
    // 4) out proj
    gemm_tc<0,0><<<dim3(18,16,1),128,SMEM_GEMM>>>(pca, DM, 0, w_out, DM, 0, b_out,
        pcap2, DM, 0, nullptr,nullptr,nullptr,0, nullptr, NROW, DM, DM);
    // 5) hl + gate logits
    hlk<<<1,128>>>(timei, hlw, hlb, phl);
    gate4<<<NROW/8,256>>>(pcap2, cgw, cgb, pclog);
    gate4<<<NROW/8,256>>>(acoustic, agw, agb, palog);
    // 6) gating + routing
    init_counts<<<1,32>>>();
    gating_kernel<<<8,256>>>(pclog, palog);
    offsets_kernel<<<1,1>>>();
    scatter_kernel<<<8,256>>>();
    // 7) MoE cap branch
    gemm_tc<1,0><<<dim3(12,16,4),128,SMEM_GEMM>>>(x, DM, 0, cw1, DM, HDM, nullptr,
        pH1, HIDN, 0, pidx,poff,pcnt,0, nullptr, NROW, HIDN, DM);
    gemm_tc<1,0><<<dim3(12,16,4),128,SMEM_GEMM>>>(x, DM, 0, cw3, DM, HDM, nullptr,
        pH3, HIDN, 0, pidx,poff,pcnt,0, nullptr, NROW, HIDN, DM);
    silumul4<<<NROW*HIDN/4/256,256>>>((const float4*)pH1,(const float4*)pH3,(float4*)pH, NROW*HIDN/4);
    gemm_tc<1,1><<<dim3(18,16,4),128,SMEM_GEMM>>>(pH, HIDN, 0, cw2, HIDN, DHI, nullptr,
        py, DM, 0, pidx,poff,pcnt,0, pcm, NROW, DM, HIDN);
    // 8) MoE ac branch
    gemm_tc<1,0><<<dim3(12,16,4),128,SMEM_GEMM>>>(x, DM, 0, aw1, DM, HDM, nullptr,
        pH1, HIDN, 0, pidx,poff,pcnt,4, nullptr, NROW, HIDN, DM);
    gemm_tc<1,0><<<dim3(12,16,4),128,SMEM_GEMM>>>(x, DM, 0, aw3, DM, HDM, nullptr,
        pH3, HIDN, 0, pidx,poff,pcnt,4, nullptr, NROW, HIDN, DM);
    silumul4<<<NROW*HIDN/4/256,256>>>((const float4*)pH1,(const float4*)pH3,(float4*)pH, NROW*HIDN/4);
    gemm_tc<1,2><<<dim3(18,16,4),128,SMEM_GEMM>>>(pH, HIDN, 0, aw2, HIDN, DHI, nullptr,
        py, DM, 0, pidx,poff,pcnt,4, pam, NROW, DM, HIDN);
    // 9) region FF
    gemm_tc<0,0><<<dim3(12,16,4),128,SMEM_GEMM>>>(py, DM, REG, fw1, DM, HDM + REG, nullptr,
        pR1, HIDN, (long long)NROW*HIDN, nullptr,nullptr,nullptr,0, nullptr, NROW, HIDN, REG);
    gemm_tc<0,0><<<dim3(12,16,4),128,SMEM_GEMM>>>(py, DM, REG, fw3, DM, HDM + REG, nullptr,
        pR3, HIDN, (long long)NROW*HIDN, nullptr,nullptr,nullptr,0, nullptr, NROW, HIDN, REG);
    silumul4<<<4*NROW*HIDN/4/256,256>>>((const float4*)pR1,(const float4*)pR3,(float4*)pR, 4*NROW*HIDN/4);
    gemm_tc<0,0><<<dim3(5,16,4),128,SMEM_GEMM>>>(pR, HIDN, (long long)NROW*HIDN, fw2, HIDN, DHI + (long long)REG*HIDN, nullptr,
        out, DM, REG, nullptr,nullptr,nullptr,0, nullptr, NROW, REG, HIDN);
    // 10) lb loss scalar
    long long zElems = (long long)NROW * DM;
    long long i1 = ((long long)out_size > zElems) ? zElems : -1;
    lb_kernel<<<1,256>>>(out, i1);
}